// round 6
// baseline (speedup 1.0000x reference)
#include <cuda_runtime.h>
#include <cuda_bf16.h>
#include <cstdint>

// ============================================================
// Problem constants
// ============================================================
#define BB    32
#define HID   128
#define ATTN  128
#define S_TOTAL   8192
#define TILE_S    128
#define TILES_PB  (S_TOTAL / TILE_S) // 64
#define CPB       8
#define TILES_PER_CTA (TILES_PB / CPB) // 8
#define NCTA      (BB * CPB)         // 256

// bf16 tile [128 rows][128 cols] with 16B row pad
#define PITCH_H   136
#define PITCH_B   (PITCH_H * 2)      // 272
#define TILE_BYTES (128 * PITCH_B)   // 34816

// SMEM layout (bytes)
#define SMEM_RED    0                      // float[8] (+ combine flag)
#define SMEM_SCORE  32                     // float[128]
#define SMEM_SW     544                    // float[2][128]
#define SMEM_CORR   1568                   // float[2]
#define SMEM_BIASV  1600                   // float2[128]
#define SMEM_A0     2624
#define SMEM_A1     (SMEM_A0 + TILE_BYTES) // 37440
#define SMEM_W      (SMEM_A1 + TILE_BYTES) // 72256
#define SMEM_TOTAL  (SMEM_W + TILE_BYTES)  // 107072

// Named barriers
#define BAR_PROD  1
#define BAR_CONS  2
#define BAR_FULL0 3
#define BAR_FULL1 4
#define BAR_DONE0 5
#define BAR_DONE1 6
#define BAR_SW0   7
#define BAR_SW1   8
#define BAR_ACC0  9
#define BAR_ACC1  10

#define BSYNC(id, n)   asm volatile("bar.sync %0, %1;"   :: "r"(id), "r"(n) : "memory")
#define BARRIVE(id, n) asm volatile("bar.arrive %0, %1;" :: "r"(id), "r"(n) : "memory")

// ============================================================
// Partial-result scratch + combine counters
// ============================================================
__device__ float g_pm[NCTA];
__device__ float g_pl[NCTA];
__device__ float g_pacc[NCTA * HID];
__device__ int   g_cnt[BB];   // zero-init; self-cleaning each launch

// ============================================================
// Helpers
// ============================================================
__device__ __forceinline__ uint32_t smem_to_u32(const void* p) {
    uint32_t a;
    asm("{ .reg .u64 t; cvta.to.shared.u64 t, %1; cvt.u32.u64 %0, t; }" : "=r"(a) : "l"(p));
    return a;
}

#define LDSM_X4(r, addr) \
    asm volatile("ldmatrix.sync.aligned.m8n8.x4.shared.b16 {%0,%1,%2,%3}, [%4];" \
        : "=r"((r)[0]), "=r"((r)[1]), "=r"((r)[2]), "=r"((r)[3]) : "r"(addr))

__device__ __forceinline__ void mma16816(float* c, const uint32_t* a, uint32_t b0, uint32_t b1) {
    asm volatile(
        "mma.sync.aligned.m16n8k16.row.col.f32.bf16.bf16.f32 "
        "{%0,%1,%2,%3}, {%4,%5,%6,%7}, {%8,%9}, {%0,%1,%2,%3};"
        : "+f"(c[0]), "+f"(c[1]), "+f"(c[2]), "+f"(c[3])
        : "r"(a[0]), "r"(a[1]), "r"(a[2]), "r"(a[3]), "r"(b0), "r"(b1));
}

__device__ __forceinline__ float bf_at(const char* p) {
    uint16_t raw = *reinterpret_cast<const uint16_t*>(p);
    return __uint_as_float(((uint32_t)raw) << 16);
}

__device__ __forceinline__ void cvt_sts(char* dst, int r, int lane, float4 v) {
    uint32_t p0, p1;
    asm("cvt.rn.bf16x2.f32 %0, %1, %2;" : "=r"(p0) : "f"(v.y), "f"(v.x));
    asm("cvt.rn.bf16x2.f32 %0, %1, %2;" : "=r"(p1) : "f"(v.w), "f"(v.z));
    *reinterpret_cast<uint2*>(dst + r * PITCH_B + lane * 8) = make_uint2(p0, p1);
}

// Full [128x128] tile load (init phase / W tile): 128 threads.
__device__ __forceinline__ void load_tile_bf16(const float4* __restrict__ src4,
                                               char* dst, int wid, int lane) {
#pragma unroll 16
    for (int it = 0; it < 32; ++it) {
        int r = it * 4 + wid;
        cvt_sts(dst, r, lane, __ldg(&src4[r * 32 + lane]));
    }
}

// Weighted accumulate over one tile: 4 independent chains.
__device__ __forceinline__ float acc_tile(const char* hb, const float* w, float facc, float corr) {
    float a0 = 0.f, a1 = 0.f, a2 = 0.f, a3 = 0.f;
#pragma unroll
    for (int s2 = 0; s2 < TILE_S; s2 += 4) {
        a0 = fmaf(w[s2 + 0], bf_at(hb + (s2 + 0) * PITCH_B), a0);
        a1 = fmaf(w[s2 + 1], bf_at(hb + (s2 + 1) * PITCH_B), a1);
        a2 = fmaf(w[s2 + 2], bf_at(hb + (s2 + 2) * PITCH_B), a2);
        a3 = fmaf(w[s2 + 3], bf_at(hb + (s2 + 3) * PITCH_B), a3);
    }
    return fmaf(facc, corr, (a0 + a1) + (a2 + a3));
}

// ============================================================
// Main fused kernel (single launch; last CTA per batch combines)
// ============================================================
__global__ void __launch_bounds__(256, 2) attn_main_kernel(
    const float* __restrict__ hist, const float* __restrict__ cur,
    const float* __restrict__ Wx,   const float* __restrict__ Wxb,
    const float* __restrict__ Wh,   const float* __restrict__ Whb,
    const float* __restrict__ vw,   float* __restrict__ out)
{
    extern __shared__ __align__(16) char smem[];
    const int tid = threadIdx.x;
    const int cta = blockIdx.x, b = cta >> 3, c = cta & 7;
    const uint32_t sbase = smem_to_u32(smem);

    float* s_red   = reinterpret_cast<float*>(smem + SMEM_RED);
    float* s_score = reinterpret_cast<float*>(smem + SMEM_SCORE);
    float* s_w     = reinterpret_cast<float*>(smem + SMEM_SW);     // [2][128]
    float* s_corr  = reinterpret_cast<float*>(smem + SMEM_CORR);   // [2]
    float2* biasv  = reinterpret_cast<float2*>(smem + SMEM_BIASV);
    char* bufA[2]  = { smem + SMEM_A0, smem + SMEM_A1 };

    const bool is_prod = (tid < 128);

    // ---------- init phase ----------
    if (is_prod) {
        // Stage Wx transposed (coalesced gmem, pad-129 smem) into A0/A1 region,
        // then bias[a] = Whb[a] + Wxb[a] + Wx[a,:].cur[b,:]
        float* stage = reinterpret_cast<float*>(smem + SMEM_A0);
#pragma unroll 16
        for (int idx = tid; idx < ATTN * HID; idx += 128) {
            int a = idx >> 7, k = idx & 127;
            stage[k * 129 + a] = __ldg(&Wx[idx]);
        }
        BSYNC(BAR_PROD, 128);
        const float* cb = cur + b * HID;
        float s0 = 0.f, s1 = 0.f, s2 = 0.f, s3 = 0.f;
#pragma unroll
        for (int k = 0; k < HID; k += 4) {
            s0 = fmaf(stage[(k + 0) * 129 + tid], __ldg(&cb[k + 0]), s0);
            s1 = fmaf(stage[(k + 1) * 129 + tid], __ldg(&cb[k + 1]), s1);
            s2 = fmaf(stage[(k + 2) * 129 + tid], __ldg(&cb[k + 2]), s2);
            s3 = fmaf(stage[(k + 3) * 129 + tid], __ldg(&cb[k + 3]), s3);
        }
        float s = Wxb[tid] + Whb[tid] + ((s0 + s1) + (s2 + s3));
        biasv[tid] = make_float2(s, __ldg(&vw[tid]));
    } else {
        const int ctid = tid - 128;
        load_tile_bf16(reinterpret_cast<const float4*>(Wh),
                       smem + SMEM_W, ctid >> 5, ctid & 31);
    }
    __syncthreads();

    const float4* histb = reinterpret_cast<const float4*>(
        hist + (size_t)b * S_TOTAL * HID);

    if (is_prod) {
        // ======================= PRODUCER =======================
        const int wid = tid >> 5, lane = tid & 31;
        float facc = 0.f;

        for (int i = 0; i < TILES_PER_CTA; ++i) {
            const int s = i & 1;
            const float4* src = histb + (size_t)(c + i * CPB) * TILE_S * 32;

            // prefetch 8 rows into regs BEFORE the buffer-free wait (gmem->reg only)
            float4 pre[8];
#pragma unroll
            for (int k2 = 0; k2 < 8; ++k2)
                pre[k2] = __ldg(&src[(k2 * 4 + wid) * 32 + lane]);

            if (i >= 2) BSYNC(BAR_DONE0 + s, 256);   // consumer done with buf s (tile i-2)

            char* dst = bufA[s];
#pragma unroll
            for (int k2 = 0; k2 < 8; ++k2)
                cvt_sts(dst, k2 * 4 + wid, lane, pre[k2]);
#pragma unroll 12
            for (int it = 8; it < 32; ++it) {
                int r = it * 4 + wid;
                cvt_sts(dst, r, lane, __ldg(&src[r * 32 + lane]));
            }
            BARRIVE(BAR_FULL0 + s, 256);             // bar.arrive release

            if (i >= 1) {
                const int p = (i - 1) & 1;
                BSYNC(BAR_SW0 + p, 256);             // weights for tile i-1 published
                facc = acc_tile(bufA[p] + tid * 2, s_w + p * 128, facc, s_corr[p]);
                BARRIVE(BAR_ACC0 + p, 256);          // slot p reusable
            }
        }
        {
            const int p = (TILES_PER_CTA - 1) & 1;
            BSYNC(BAR_SW0 + p, 256);
            facc = acc_tile(bufA[p] + tid * 2, s_w + p * 128, facc, s_corr[p]);
        }
        g_pacc[cta * HID + tid] = facc;
    } else {
        // ======================= CONSUMER =======================
        const int ctid = tid - 128;
        const int cw = ctid >> 5, lane = ctid & 31;
        const uint32_t sW = sbase + SMEM_W;

        const int g8 = lane & 7;
        const uint32_t rowA_off = (uint32_t)((((lane >> 3) & 1) * 8 + g8) * PITCH_B + (lane >> 4) * 16);
        const uint32_t rowB_off = (uint32_t)(((lane >> 4) * 8 + g8) * PITCH_B + ((lane >> 3) & 1) * 16);

        float m_run = __int_as_float(0xff800000);
        float l_run = 0.f;

        for (int i = 0; i < TILES_PER_CTA; ++i) {
            const int s = i & 1;
            BSYNC(BAR_FULL0 + s, 256);
            const uint32_t sA = sbase + (s ? SMEM_A1 : SMEM_A0);

            // ---- GEMM in two 64-col halves: A frags loaded once per half ----
            float sp[2][2] = {{0.f, 0.f}, {0.f, 0.f}};
#pragma unroll
            for (int h = 0; h < 2; ++h) {
                float acc[2][8][4];
#pragma unroll
                for (int mt = 0; mt < 2; ++mt)
#pragma unroll
                    for (int nt = 0; nt < 8; ++nt)
#pragma unroll
                        for (int r = 0; r < 4; ++r) acc[mt][nt][r] = 0.f;
#pragma unroll
                for (int k = 0; k < 8; ++k) {
                    uint32_t afr[2][4], bfr[4][4];
#pragma unroll
                    for (int mt = 0; mt < 2; ++mt)
                        LDSM_X4(afr[mt], sA + (uint32_t)((cw * 32 + mt * 16) * PITCH_B + k * 32) + rowA_off);
#pragma unroll
                    for (int q = 0; q < 4; ++q)
                        LDSM_X4(bfr[q], sW + (uint32_t)((h * 64 + q * 16) * PITCH_B + k * 32) + rowB_off);
#pragma unroll
                    for (int mt = 0; mt < 2; ++mt)
#pragma unroll
                        for (int nt = 0; nt < 8; ++nt)
                            mma16816(acc[mt][nt], afr[mt],
                                     bfr[nt >> 1][(nt & 1) * 2], bfr[nt >> 1][(nt & 1) * 2 + 1]);
                }
                // epilogue for these 64 cols: tanh(x+bias)*v reduce
#pragma unroll
                for (int mt = 0; mt < 2; ++mt)
#pragma unroll
                    for (int nt = 0; nt < 8; ++nt) {
                        const int colb = h * 64 + nt * 8 + 2 * (lane & 3);
                        const float2 bv0 = biasv[colb];
                        const float2 bv1 = biasv[colb + 1];
#pragma unroll
                        for (int rr = 0; rr < 2; ++rr) {
                            float x0 = acc[mt][nt][rr * 2 + 0] + bv0.x;
                            float x1 = acc[mt][nt][rr * 2 + 1] + bv1.x;
                            float t0, t1;
                            asm("tanh.approx.f32 %0, %1;" : "=f"(t0) : "f"(x0));
                            asm("tanh.approx.f32 %0, %1;" : "=f"(t1) : "f"(x1));
                            sp[mt][rr] = fmaf(t0, bv0.y, sp[mt][rr]);
                            sp[mt][rr] = fmaf(t1, bv1.y, sp[mt][rr]);
                        }
                    }
            }
            BARRIVE(BAR_DONE0 + s, 256);   // all A reads done; buf s free

            // ---- scores -> smem (warp-local scatter) ----
#pragma unroll
            for (int mt = 0; mt < 2; ++mt)
#pragma unroll
                for (int rr = 0; rr < 2; ++rr) {
                    float v = sp[mt][rr];
                    v += __shfl_xor_sync(0xffffffffu, v, 1);
                    v += __shfl_xor_sync(0xffffffffu, v, 2);
                    if ((lane & 3) == 0)
                        s_score[cw * 32 + mt * 16 + rr * 8 + (lane >> 2)] = v;
                }
            __syncwarp();
            const float score = s_score[ctid];

            // ---- block max ----
            float mt_ = score;
#pragma unroll
            for (int o = 16; o; o >>= 1) mt_ = fmaxf(mt_, __shfl_xor_sync(0xffffffffu, mt_, o));
            if (lane == 0) s_red[cw] = mt_;
            BSYNC(BAR_CONS, 128);
            const float tmax  = fmaxf(fmaxf(s_red[0], s_red[1]), fmaxf(s_red[2], s_red[3]));
            const float new_m = fmaxf(m_run, tmax);
            const float corr  = __expf(m_run - new_m);
            const float p     = __expf(score - new_m);

            // publish weight (slot guarded by ACC from tile i-2)
            if (i >= 2) BSYNC(BAR_ACC0 + s, 256);
            s_w[s * 128 + ctid] = p;
            if (ctid == 0) s_corr[s] = corr;

            // ---- block sum (same sync fences the s_w stores) ----
            float ps = p;
#pragma unroll
            for (int o = 16; o; o >>= 1) ps += __shfl_xor_sync(0xffffffffu, ps, o);
            if (lane == 0) s_red[4 + cw] = ps;
            BSYNC(BAR_CONS, 128);
            l_run = l_run * corr + (s_red[4] + s_red[5] + s_red[6] + s_red[7]);
            m_run = new_m;
            BARRIVE(BAR_SW0 + s, 256);
        }
        if (ctid == 0) { g_pm[cta] = m_run; g_pl[cta] = l_run; }
    }

    // ---------- last-CTA-per-batch combine ----------
    __threadfence();
    __syncthreads();
    int* s_flag = reinterpret_cast<int*>(smem + SMEM_RED);
    if (tid == 0) {
        int old = atomicAdd(&g_cnt[b], 1);
        s_flag[0] = (old == CPB - 1) ? 1 : 0;
    }
    __syncthreads();
    if (s_flag[0]) {
        __threadfence();
        if (tid < HID) {
            float M = __int_as_float(0xff800000);
            float pm[CPB], pl[CPB];
#pragma unroll
            for (int j = 0; j < CPB; ++j) {
                pm[j] = __ldcg(&g_pm[b * CPB + j]);
                pl[j] = __ldcg(&g_pl[b * CPB + j]);
                M = fmaxf(M, pm[j]);
            }
            float L = 0.f, num = 0.f;
#pragma unroll
            for (int j = 0; j < CPB; ++j) {
                const float e = __expf(pm[j] - M);
                L   += pl[j] * e;
                num += __ldcg(&g_pacc[(b * CPB + j) * HID + tid]) * e;
            }
            out[b * HID + tid] = cur[b * HID + tid] + num / L;
        }
        if (tid == 0) g_cnt[b] = 0;   // reset for next graph replay
    }
}

// ============================================================
// Launch
// ============================================================
extern "C" void kernel_launch(void* const* d_in, const int* in_sizes, int n_in,
                              void* d_out, int out_size)
{
    (void)in_sizes; (void)n_in; (void)out_size;
    const float* cur  = (const float*)d_in[0];
    const float* hist = (const float*)d_in[1];
    const float* Wx   = (const float*)d_in[2];
    const float* Wxb  = (const float*)d_in[3];
    const float* Wh   = (const float*)d_in[4];
    const float* Whb  = (const float*)d_in[5];
    const float* vw   = (const float*)d_in[6];
    float* out = (float*)d_out;

    cudaFuncSetAttribute(attn_main_kernel,
                         cudaFuncAttributeMaxDynamicSharedMemorySize, SMEM_TOTAL);

    attn_main_kernel<<<NCTA, 256, SMEM_TOTAL>>>(hist, cur, Wx, Wxb, Wh, Whb, vw, out);
}

// round 7
// speedup vs baseline: 1.1397x; 1.1397x over previous
#include <cuda_runtime.h>
#include <cuda_bf16.h>
#include <cstdint>

// ============================================================
// Problem constants
// ============================================================
#define BB    32
#define HID   128
#define ATTN  128
#define S_TOTAL   8192
#define TILE_S    128
#define TILES_PB  (S_TOTAL / TILE_S) // 64
#define CPB       8
#define TILES_PER_CTA (TILES_PB / CPB) // 8
#define NCTA      (BB * CPB)         // 256

// bf16 tile [128 rows][128 cols] with 16B row pad
#define PITCH_H   136
#define PITCH_B   (PITCH_H * 2)      // 272
#define TILE_BYTES (128 * PITCH_B)   // 34816

// SMEM layout (bytes)
#define SMEM_RED    0                      // float[8] (+ combine flag)
#define SMEM_SCORE  32                     // float[128]
#define SMEM_SW     544                    // float[2][128]
#define SMEM_MB     1568                   // float[1]: M_bound
#define SMEM_BIASV  1600                   // float2[128]
#define SMEM_A0     2624
#define SMEM_A1     (SMEM_A0 + TILE_BYTES) // 37440
#define SMEM_W      (SMEM_A1 + TILE_BYTES) // 72256
#define SMEM_TOTAL  (SMEM_W + TILE_BYTES)  // 107072

// Named barriers
#define BAR_PROD  1
#define BAR_CONS  2
#define BAR_FULL0 3
#define BAR_FULL1 4
#define BAR_DONE0 5
#define BAR_DONE1 6
#define BAR_SW0   7
#define BAR_SW1   8
#define BAR_ACC0  9
#define BAR_ACC1  10

#define BSYNC(id, n)   asm volatile("bar.sync %0, %1;"   :: "r"(id), "r"(n) : "memory")
#define BARRIVE(id, n) asm volatile("bar.arrive %0, %1;" :: "r"(id), "r"(n) : "memory")

// ============================================================
// Partial-result scratch + combine counters
// ============================================================
__device__ float g_pl[NCTA];
__device__ float g_pacc[NCTA * HID];
__device__ int   g_cnt[BB];   // zero-init; self-cleaning each launch

// ============================================================
// Helpers
// ============================================================
__device__ __forceinline__ uint32_t smem_to_u32(const void* p) {
    uint32_t a;
    asm("{ .reg .u64 t; cvta.to.shared.u64 t, %1; cvt.u32.u64 %0, t; }" : "=r"(a) : "l"(p));
    return a;
}

#define LDSM_X4(r, addr) \
    asm volatile("ldmatrix.sync.aligned.m8n8.x4.shared.b16 {%0,%1,%2,%3}, [%4];" \
        : "=r"((r)[0]), "=r"((r)[1]), "=r"((r)[2]), "=r"((r)[3]) : "r"(addr))

__device__ __forceinline__ void mma16816(float* c, const uint32_t* a, uint32_t b0, uint32_t b1) {
    asm volatile(
        "mma.sync.aligned.m16n8k16.row.col.f32.bf16.bf16.f32 "
        "{%0,%1,%2,%3}, {%4,%5,%6,%7}, {%8,%9}, {%0,%1,%2,%3};"
        : "+f"(c[0]), "+f"(c[1]), "+f"(c[2]), "+f"(c[3])
        : "r"(a[0]), "r"(a[1]), "r"(a[2]), "r"(a[3]), "r"(b0), "r"(b1));
}

__device__ __forceinline__ float bf_at(const char* p) {
    uint16_t raw = *reinterpret_cast<const uint16_t*>(p);
    return __uint_as_float(((uint32_t)raw) << 16);
}

__device__ __forceinline__ void cvt_sts(char* dst, int r, int lane, float4 v) {
    uint32_t p0, p1;
    asm("cvt.rn.bf16x2.f32 %0, %1, %2;" : "=r"(p0) : "f"(v.y), "f"(v.x));
    asm("cvt.rn.bf16x2.f32 %0, %1, %2;" : "=r"(p1) : "f"(v.w), "f"(v.z));
    *reinterpret_cast<uint2*>(dst + r * PITCH_B + lane * 8) = make_uint2(p0, p1);
}

// Full [128x128] tile load (W tile): 128 threads.
__device__ __forceinline__ void load_tile_bf16(const float4* __restrict__ src4,
                                               char* dst, int wid, int lane) {
#pragma unroll 16
    for (int it = 0; it < 32; ++it) {
        int r = it * 4 + wid;
        cvt_sts(dst, r, lane, __ldg(&src4[r * 32 + lane]));
    }
}

// Weighted accumulate over one tile: pure sum, 4 independent chains.
__device__ __forceinline__ float acc_tile(const char* hb, const float* w, float facc) {
    float a0 = 0.f, a1 = 0.f, a2 = 0.f, a3 = 0.f;
#pragma unroll
    for (int s2 = 0; s2 < TILE_S; s2 += 4) {
        a0 = fmaf(w[s2 + 0], bf_at(hb + (s2 + 0) * PITCH_B), a0);
        a1 = fmaf(w[s2 + 1], bf_at(hb + (s2 + 1) * PITCH_B), a1);
        a2 = fmaf(w[s2 + 2], bf_at(hb + (s2 + 2) * PITCH_B), a2);
        a3 = fmaf(w[s2 + 3], bf_at(hb + (s2 + 3) * PITCH_B), a3);
    }
    return facc + ((a0 + a1) + (a2 + a3));
}

// ============================================================
// Main fused kernel (single launch; last CTA per batch combines)
// ============================================================
__global__ void __launch_bounds__(256, 2) attn_main_kernel(
    const float* __restrict__ hist, const float* __restrict__ cur,
    const float* __restrict__ Wx,   const float* __restrict__ Wxb,
    const float* __restrict__ Wh,   const float* __restrict__ Whb,
    const float* __restrict__ vw,   float* __restrict__ out)
{
    extern __shared__ __align__(16) char smem[];
    const int tid = threadIdx.x;
    const int cta = blockIdx.x, b = cta >> 3, c = cta & 7;
    const uint32_t sbase = smem_to_u32(smem);

    float* s_red   = reinterpret_cast<float*>(smem + SMEM_RED);
    float* s_score = reinterpret_cast<float*>(smem + SMEM_SCORE);
    float* s_w     = reinterpret_cast<float*>(smem + SMEM_SW);     // [2][128]
    float* s_mb    = reinterpret_cast<float*>(smem + SMEM_MB);     // M_bound
    float2* biasv  = reinterpret_cast<float2*>(smem + SMEM_BIASV);
    char* bufA[2]  = { smem + SMEM_A0, smem + SMEM_A1 };

    const bool is_prod = (tid < 128);

    // ---------- init phase ----------
    if (is_prod) {
        const int wid = tid >> 5, lane = tid & 31;
        // Stage Wx transposed (coalesced gmem, pad-129 smem) into A region,
        // then bias[a] = Whb[a] + Wxb[a] + Wx[a,:].cur[b,:]
        float* stage = reinterpret_cast<float*>(smem + SMEM_A0);
#pragma unroll 16
        for (int idx = tid; idx < ATTN * HID; idx += 128) {
            int a = idx >> 7, k = idx & 127;
            stage[k * 129 + a] = __ldg(&Wx[idx]);
        }
        BSYNC(BAR_PROD, 128);
        const float* cb = cur + b * HID;
        float s0 = 0.f, s1 = 0.f, s2 = 0.f, s3 = 0.f;
#pragma unroll
        for (int k = 0; k < HID; k += 4) {
            s0 = fmaf(stage[(k + 0) * 129 + tid], __ldg(&cb[k + 0]), s0);
            s1 = fmaf(stage[(k + 1) * 129 + tid], __ldg(&cb[k + 1]), s1);
            s2 = fmaf(stage[(k + 2) * 129 + tid], __ldg(&cb[k + 2]), s2);
            s3 = fmaf(stage[(k + 3) * 129 + tid], __ldg(&cb[k + 3]), s3);
        }
        const float vwi = __ldg(&vw[tid]);
        float s = Wxb[tid] + Whb[tid] + ((s0 + s1) + (s2 + s3));
        biasv[tid] = make_float2(s, vwi);
        // M_bound = sum over a of |v_a|   (static softmax max)
        float av = fabsf(vwi);
#pragma unroll
        for (int o = 16; o; o >>= 1) av += __shfl_xor_sync(0xffffffffu, av, o);
        if (lane == 0) s_red[wid] = av;
        BSYNC(BAR_PROD, 128);
        if (tid == 0) s_mb[0] = (s_red[0] + s_red[1]) + (s_red[2] + s_red[3]);
    } else {
        const int ctid = tid - 128;
        load_tile_bf16(reinterpret_cast<const float4*>(Wh),
                       smem + SMEM_W, ctid >> 5, ctid & 31);
    }
    __syncthreads();
    const float M_bound = s_mb[0];

    const float4* histb = reinterpret_cast<const float4*>(
        hist + (size_t)b * S_TOTAL * HID);

    if (is_prod) {
        // ======================= PRODUCER =======================
        const int wid = tid >> 5, lane = tid & 31;
        float facc = 0.f;

        for (int i = 0; i < TILES_PER_CTA; ++i) {
            const int s = i & 1;
            const float4* src = histb + (size_t)(c + i * CPB) * TILE_S * 32;

            // prefetch 12 rows into regs BEFORE the buffer-free wait
            float4 pre[12];
#pragma unroll
            for (int k2 = 0; k2 < 12; ++k2)
                pre[k2] = __ldg(&src[(k2 * 4 + wid) * 32 + lane]);

            if (i >= 2) BSYNC(BAR_DONE0 + s, 256);

            char* dst = bufA[s];
#pragma unroll
            for (int k2 = 0; k2 < 12; ++k2)
                cvt_sts(dst, k2 * 4 + wid, lane, pre[k2]);
#pragma unroll 10
            for (int it = 12; it < 32; ++it) {
                int r = it * 4 + wid;
                cvt_sts(dst, r, lane, __ldg(&src[r * 32 + lane]));
            }
            BARRIVE(BAR_FULL0 + s, 256);

            if (i >= 1) {
                const int p = (i - 1) & 1;
                BSYNC(BAR_SW0 + p, 256);             // weights for tile i-1 published
                facc = acc_tile(bufA[p] + tid * 2, s_w + p * 128, facc);
                BARRIVE(BAR_ACC0 + p, 256);          // slot p reusable
            }
        }
        {
            const int p = (TILES_PER_CTA - 1) & 1;
            BSYNC(BAR_SW0 + p, 256);
            facc = acc_tile(bufA[p] + tid * 2, s_w + p * 128, facc);
        }
        g_pacc[cta * HID + tid] = facc;
    } else {
        // ======================= CONSUMER =======================
        const int ctid = tid - 128;
        const int cw = ctid >> 5, lane = ctid & 31;
        const uint32_t sW = sbase + SMEM_W;

        const int g8 = lane & 7;
        const uint32_t rowA_off = (uint32_t)((((lane >> 3) & 1) * 8 + g8) * PITCH_B + (lane >> 4) * 16);
        const uint32_t rowB_off = (uint32_t)(((lane >> 4) * 8 + g8) * PITCH_B + ((lane >> 3) & 1) * 16);

        float l_run = 0.f;

        for (int i = 0; i < TILES_PER_CTA; ++i) {
            const int s = i & 1;
            BSYNC(BAR_FULL0 + s, 256);
            const uint32_t sA = sbase + (s ? SMEM_A1 : SMEM_A0);

            // ---- GEMM (R5 structure: nc chunks, 32 acc regs) ----
            float sp[2][2] = {{0.f, 0.f}, {0.f, 0.f}};
#pragma unroll
            for (int nc = 0; nc < 4; ++nc) {
                float acc[2][4][4];
#pragma unroll
                for (int mt = 0; mt < 2; ++mt)
#pragma unroll
                    for (int nt = 0; nt < 4; ++nt)
#pragma unroll
                        for (int r = 0; r < 4; ++r) acc[mt][nt][r] = 0.f;
#pragma unroll
                for (int k = 0; k < 8; ++k) {
                    uint32_t afr[2][4], bfr[2][4];
#pragma unroll
                    for (int mt = 0; mt < 2; ++mt)
                        LDSM_X4(afr[mt], sA + (uint32_t)((cw * 32 + mt * 16) * PITCH_B + k * 32) + rowA_off);
#pragma unroll
                    for (int ntp = 0; ntp < 2; ++ntp)
                        LDSM_X4(bfr[ntp], sW + (uint32_t)((nc * 32 + ntp * 16) * PITCH_B + k * 32) + rowB_off);
#pragma unroll
                    for (int mt = 0; mt < 2; ++mt)
#pragma unroll
                        for (int nt = 0; nt < 4; ++nt)
                            mma16816(acc[mt][nt], afr[mt],
                                     bfr[nt >> 1][(nt & 1) * 2], bfr[nt >> 1][(nt & 1) * 2 + 1]);
                }
#pragma unroll
                for (int mt = 0; mt < 2; ++mt)
#pragma unroll
                    for (int nt = 0; nt < 4; ++nt) {
                        const int colb = nc * 32 + nt * 8 + 2 * (lane & 3);
                        const float2 bv0 = biasv[colb];
                        const float2 bv1 = biasv[colb + 1];
#pragma unroll
                        for (int rr = 0; rr < 2; ++rr) {
                            float x0 = acc[mt][nt][rr * 2 + 0] + bv0.x;
                            float x1 = acc[mt][nt][rr * 2 + 1] + bv1.x;
                            float t0, t1;
                            asm("tanh.approx.f32 %0, %1;" : "=f"(t0) : "f"(x0));
                            asm("tanh.approx.f32 %0, %1;" : "=f"(t1) : "f"(x1));
                            sp[mt][rr] = fmaf(t0, bv0.y, sp[mt][rr]);
                            sp[mt][rr] = fmaf(t1, bv1.y, sp[mt][rr]);
                        }
                    }
            }
            BARRIVE(BAR_DONE0 + s, 256);   // A reads done; buf s free

            // ---- scores -> smem (warp-local scatter) ----
#pragma unroll
            for (int mt = 0; mt < 2; ++mt)
#pragma unroll
                for (int rr = 0; rr < 2; ++rr) {
                    float v = sp[mt][rr];
                    v += __shfl_xor_sync(0xffffffffu, v, 1);
                    v += __shfl_xor_sync(0xffffffffu, v, 2);
                    if ((lane & 3) == 0)
                        s_score[cw * 32 + mt * 16 + rr * 8 + (lane >> 2)] = v;
                }
            __syncwarp();

            // ---- static-max softmax: p = exp(score - M_bound) ----
            const float p = __expf(s_score[ctid] - M_bound);

            if (i >= 2) BSYNC(BAR_ACC0 + s, 256);    // slot s free (tile i-2 consumed)
            s_w[s * 128 + ctid] = p;

            // single block-sum reduction (also fences s_w stores)
            float ps = p;
#pragma unroll
            for (int o = 16; o; o >>= 1) ps += __shfl_xor_sync(0xffffffffu, ps, o);
            if (lane == 0) s_red[4 + cw] = ps;
            BSYNC(BAR_CONS, 128);
            l_run += (s_red[4] + s_red[5]) + (s_red[6] + s_red[7]);
            BARRIVE(BAR_SW0 + s, 256);
        }
        if (ctid == 0) g_pl[cta] = l_run;
    }

    // ---------- last-CTA-per-batch combine ----------
    __threadfence();
    __syncthreads();
    int* s_flag = reinterpret_cast<int*>(smem + SMEM_RED);
    if (tid == 0) {
        int old = atomicAdd(&g_cnt[b], 1);
        s_flag[0] = (old == CPB - 1) ? 1 : 0;
    }
    __syncthreads();
    if (s_flag[0]) {
        __threadfence();
        if (tid < HID) {
            float L = 0.f, num = 0.f;
#pragma unroll
            for (int j = 0; j < CPB; ++j) {
                L   += __ldcg(&g_pl[b * CPB + j]);
                num += __ldcg(&g_pacc[(b * CPB + j) * HID + tid]);
            }
            out[b * HID + tid] = cur[b * HID + tid] + num / L;
        }
        if (tid == 0) g_cnt[b] = 0;   // reset for next graph replay
    }
}

// ============================================================
// Launch
// ============================================================
extern "C" void kernel_launch(void* const* d_in, const int* in_sizes, int n_in,
                              void* d_out, int out_size)
{
    (void)in_sizes; (void)n_in; (void)out_size;
    const float* cur  = (const float*)d_in[0];
    const float* hist = (const float*)d_in[1];
    const float* Wx   = (const float*)d_in[2];
    const float* Wxb  = (const float*)d_in[3];
    const float* Wh   = (const float*)d_in[4];
    const float* Whb  = (const float*)d_in[5];
    const float* vw   = (const float*)d_in[6];
    float* out = (float*)d_out;

    cudaFuncSetAttribute(attn_main_kernel,
                         cudaFuncAttributeMaxDynamicSharedMemorySize, SMEM_TOTAL);

    attn_main_kernel<<<NCTA, 256, SMEM_TOTAL>>>(hist, cur, Wx, Wxb, Wh, Whb, vw, out);
}